// round 4
// baseline (speedup 1.0000x reference)
#include <cuda_runtime.h>

// NCELoss: N=4096 examples, E=1024 embed, K=50 noise samples (+1 target).
// Inputs (metadata order):
//   d_in[0] input  f32 [N,E]
//   d_in[1] target i32 [N]
//   d_in[2] noise_samples i32 [N,K]
//   d_in[3] noise  f32 [V]
//   d_in[4] weight f32 [V,E]
//   d_in[5] bias   f32 [V]
// Output: scalar f32 loss.
//
// Fused single kernel. Per-block partial -> __device__ array; last block
// (atomic ticket, self-resetting for graph replay) reduces in double.
// Weight rows use 256-bit loads with L2::evict_last (sm_103 requires v8.b32
// for that policy) to maximize residency of the reused weight stream.

#define EDIM 1024
#define KNOISE 50
#define NORM_TERM 9.0f
#define NWARPS 8
#define MAXN 8192

__device__ double        g_partial[MAXN];
__device__ unsigned int  g_done = 0;

// 256-bit global load (8 floats), non-coherent, L2 evict_last policy.
__device__ __forceinline__ void ldg256_evict_last(const float* p, float v[8]) {
    unsigned int r0, r1, r2, r3, r4, r5, r6, r7;
    asm volatile("ld.global.nc.L2::evict_last.v8.b32 "
                 "{%0,%1,%2,%3,%4,%5,%6,%7}, [%8];"
                 : "=r"(r0), "=r"(r1), "=r"(r2), "=r"(r3),
                   "=r"(r4), "=r"(r5), "=r"(r6), "=r"(r7)
                 : "l"(p));
    v[0] = __uint_as_float(r0); v[1] = __uint_as_float(r1);
    v[2] = __uint_as_float(r2); v[3] = __uint_as_float(r3);
    v[4] = __uint_as_float(r4); v[5] = __uint_as_float(r5);
    v[6] = __uint_as_float(r6); v[7] = __uint_as_float(r7);
}

__device__ __forceinline__ float loss_term(int j, int idx, float s,
                                           const float* __restrict__ bias,
                                           const float* __restrict__ noise)
{
    const float logit = s + __ldg(&bias[idx]);
    const float p  = expf(logit - NORM_TERM);
    const float kp = (float)KNOISE * __ldg(&noise[idx]);
    const float num = (j == 0) ? p : kp;   // j==0: data term, else noise term
    return logf(num / (p + kp));
}

__global__ __launch_bounds__(NWARPS * 32) void nce_loss_kernel(
    const float* __restrict__ input,
    const int*   __restrict__ target,
    const int*   __restrict__ noise_samples,
    const float* __restrict__ noise,
    const float* __restrict__ weight,
    const float* __restrict__ bias,
    float*       __restrict__ out,
    int N)
{
    __shared__ float4 s_in[EDIM / 4];      // 4 KB: this example's input row
    __shared__ float  s_wsum[NWARPS];
    __shared__ bool   s_is_last;

    const int n    = blockIdx.x;
    const int tid  = threadIdx.x;
    const int lane = tid & 31;
    const int wid  = tid >> 5;

    // Stage input row into smem (vectorized, coalesced).
    const float4* in4 = reinterpret_cast<const float4*>(input + (size_t)n * EDIM);
    #pragma unroll
    for (int i = tid; i < EDIM / 4; i += NWARPS * 32) s_in[i] = in4[i];
    __syncthreads();

    // Each warp handles columns j = wid, wid+8, ... over [0, K+1).
    // Per column: 4 x LDG.256 per lane (lane covers 8 floats per load,
    // warp covers 256 floats per load, 4 loads cover the 1024-float row).
    float acc = 0.0f;
    for (int j = wid; j < KNOISE + 1; j += NWARPS) {
        const int idx = (j == 0) ? __ldg(&target[n])
                                 : __ldg(&noise_samples[n * KNOISE + (j - 1)]);
        const float* wrow = weight + (size_t)idx * EDIM;

        float w[4][8];
        #pragma unroll
        for (int i = 0; i < 4; i++)
            ldg256_evict_last(wrow + i * 256 + lane * 8, w[i]);

        float s = 0.0f;
        #pragma unroll
        for (int i = 0; i < 4; i++) {
            const float4 x0 = s_in[i * 64 + lane * 2 + 0];
            const float4 x1 = s_in[i * 64 + lane * 2 + 1];
            s += w[i][0] * x0.x + w[i][1] * x0.y + w[i][2] * x0.z + w[i][3] * x0.w;
            s += w[i][4] * x1.x + w[i][5] * x1.y + w[i][6] * x1.z + w[i][7] * x1.w;
        }
        #pragma unroll
        for (int o = 16; o; o >>= 1) s += __shfl_xor_sync(0xffffffffu, s, o);

        if (lane == 0) acc += loss_term(j, idx, s, bias, noise);
    }

    if (lane == 0) s_wsum[wid] = acc;
    __syncthreads();

    if (wid == 0) {
        float v = (lane < NWARPS) ? s_wsum[lane] : 0.0f;
        #pragma unroll
        for (int o = NWARPS / 2; o; o >>= 1) v += __shfl_xor_sync(0xffffffffu, v, o);
        if (lane == 0) g_partial[n] = (double)v;
    }

    // Completion ticket: last block to arrive does the final reduction.
    if (tid == 0) {
        __threadfence();
        unsigned int prev = atomicAdd(&g_done, 1u);
        s_is_last = (prev == (unsigned int)(gridDim.x - 1));
    }
    __syncthreads();

    if (s_is_last) {
        // Fixed-order deterministic reduction over N partials, in double.
        double d = 0.0;
        for (int i = tid; i < N; i += NWARPS * 32) {
            double val;
            asm volatile("ld.global.cg.f64 %0, [%1];"
                         : "=d"(val) : "l"(g_partial + i));
            d += val;
        }
        #pragma unroll
        for (int o = 16; o; o >>= 1)
            d += __shfl_xor_sync(0xffffffffu, d, o);
        __shared__ double s_dsum[NWARPS];
        if (lane == 0) s_dsum[wid] = d;
        __syncthreads();
        if (wid == 0) {
            double t = (lane < NWARPS) ? s_dsum[lane] : 0.0;
            #pragma unroll
            for (int o = NWARPS / 2; o; o >>= 1)
                t += __shfl_xor_sync(0xffffffffu, t, o);
            if (lane == 0) {
                out[0] = (float)(-t / (double)N);
                g_done = 0u;                      // reset for next graph replay
            }
        }
    }
}

extern "C" void kernel_launch(void* const* d_in, const int* in_sizes, int n_in,
                              void* d_out, int out_size) {
    const float* input         = (const float*)d_in[0];
    const int*   target        = (const int*)  d_in[1];
    const int*   noise_samples = (const int*)  d_in[2];
    const float* noise         = (const float*)d_in[3];
    const float* weight        = (const float*)d_in[4];
    const float* bias          = (const float*)d_in[5];
    float* out = (float*)d_out;

    const int N = in_sizes[1];  // target element count

    nce_loss_kernel<<<N, NWARPS * 32>>>(input, target, noise_samples, noise,
                                        weight, bias, out, N);
}